// round 1
// baseline (speedup 1.0000x reference)
#include <cuda_runtime.h>

#define NV 500000
#define CC 8
#define KK 27

// Intermediate ping-pong buffers for both grids: [2N, 8] each (32 MB each).
__device__ float g_t1[2 * NV * CC];
__device__ float g_t2[2 * NV * CC];

// LAYER 0: in = feats (per grid), out = g_t1, ReLU
// LAYER 1: in = g_t1,             out = g_t2, ReLU
// LAYER 2: in = g_t2,             out = d_out, + residual(feats)
template <int LAYER>
__global__ void __launch_bounds__(256)
sconv_kernel(const float* __restrict__ feats0, const float* __restrict__ feats1,
             const float* __restrict__ W0, const float* __restrict__ W1,
             const int* __restrict__ nbr0, const int* __restrict__ nbr1,
             float* __restrict__ out)
{
    // Stage this layer's weights for both grids into smem: 2 * 27*64 floats.
    __shared__ float sw[2][KK * CC * CC];
    {
        const float* w0 = W0 + LAYER * KK * CC * CC;
        const float* w1 = W1 + LAYER * KK * CC * CC;
        for (int t = threadIdx.x; t < KK * CC * CC; t += blockDim.x) {
            sw[0][t] = w0[t];
            sw[1][t] = w1[t];
        }
    }
    __syncthreads();

    long long row = (long long)blockIdx.x * blockDim.x + threadIdx.x;
    if (row >= 2LL * NV) return;

    const int g = (row >= NV) ? 1 : 0;
    const int i = (int)(row - (g ? NV : 0));

    const float* xin;
    if (LAYER == 0)      xin = g ? feats1 : feats0;
    else if (LAYER == 1) xin = g_t1 + (size_t)g * NV * CC;
    else                 xin = g_t2 + (size_t)g * NV * CC;

    const int*   nb = (g ? nbr1 : nbr0) + (size_t)i * KK;
    const float* w  = sw[g];

    float acc[CC];
#pragma unroll
    for (int d = 0; d < CC; d++) acc[d] = 0.0f;

#pragma unroll 1
    for (int k = 0; k < KK; k++) {
        int idx = nb[k];
        if (idx >= 0) {
            const float4* gp = (const float4*)(xin + (size_t)idx * CC);
            float4 a = gp[0];
            float4 b = gp[1];
            float gv[CC] = {a.x, a.y, a.z, a.w, b.x, b.y, b.z, b.w};
            const float* wk = w + k * CC * CC;
#pragma unroll
            for (int c = 0; c < CC; c++) {
#pragma unroll
                for (int d = 0; d < CC; d++) {
                    acc[d] = fmaf(gv[c], wk[c * CC + d], acc[d]);
                }
            }
        }
    }

    if (LAYER < 2) {
#pragma unroll
        for (int d = 0; d < CC; d++) acc[d] = fmaxf(acc[d], 0.0f);
    } else {
        const float* r = (g ? feats1 : feats0) + (size_t)i * CC;
#pragma unroll
        for (int d = 0; d < CC; d++) acc[d] += r[d];
    }

    float* op = (LAYER == 0) ? g_t1 : (LAYER == 1) ? g_t2 : out;
    float4* o4 = (float4*)(op + (size_t)row * CC);
    o4[0] = make_float4(acc[0], acc[1], acc[2], acc[3]);
    o4[1] = make_float4(acc[4], acc[5], acc[6], acc[7]);
}

extern "C" void kernel_launch(void* const* d_in, const int* in_sizes, int n_in,
                              void* d_out, int out_size)
{
    const float* feats0 = (const float*)d_in[0];
    const float* feats1 = (const float*)d_in[1];
    const float* W0     = (const float*)d_in[2];
    const float* W1     = (const float*)d_in[3];
    const int*   nbr0   = (const int*)d_in[4];
    const int*   nbr1   = (const int*)d_in[5];
    float*       out    = (float*)d_out;

    const int threads = 256;
    const int blocks  = (2 * NV + threads - 1) / threads;

    sconv_kernel<0><<<blocks, threads>>>(feats0, feats1, W0, W1, nbr0, nbr1, out);
    sconv_kernel<1><<<blocks, threads>>>(feats0, feats1, W0, W1, nbr0, nbr1, out);
    sconv_kernel<2><<<blocks, threads>>>(feats0, feats1, W0, W1, nbr0, nbr1, out);
}

// round 2
// speedup vs baseline: 1.0478x; 1.0478x over previous
#include <cuda_runtime.h>

#define NV 500000
#define CC 8
#define KK 27

// Ping-pong intermediates for both grids: [2N, 8] each.
__device__ float g_t1[2 * NV * CC];
__device__ float g_t2[2 * NV * CC];
// Transposed neighbor maps: [grid][tap][voxel] for coalesced tap loads.
__device__ int g_nbrt[2][KK * NV];

// ---------------------------------------------------------------------------
// Transpose [N,27] row-major neighbor map into [27,N] tap-major.
// 32 rows per block; both read and write coalesced via padded smem tile.
// NV % 32 == 0 (500000 = 15625 * 32), so no tail handling needed.
// ---------------------------------------------------------------------------
__global__ void __launch_bounds__(256)
nbr_transpose_kernel(const int* __restrict__ nbr0, const int* __restrict__ nbr1)
{
    __shared__ int tile[32][29];  // pad 29: stride gcd(29,32)=1, conflict-free
    const int g = blockIdx.y;
    const int* __restrict__ src = g ? nbr1 : nbr0;
    const int base = blockIdx.x * 32;

    // Read 32*27 = 864 contiguous ints, coalesced.
    for (int t = threadIdx.x; t < 32 * KK; t += blockDim.x)
        tile[t / KK][t % KK] = src[(size_t)base * KK + t];
    __syncthreads();

    // Write tap-major: t -> (k = t/32, r = t%32); consecutive r coalesced.
    int* __restrict__ dst = g_nbrt[g];
    for (int t = threadIdx.x; t < 32 * KK; t += blockDim.x) {
        int k = t / 32, r = t % 32;
        dst[(size_t)k * NV + base + r] = tile[r][k];
    }
}

// ---------------------------------------------------------------------------
// One layer of the sparse conv for both grids.
// LAYER 0: in = feats,  out = g_t1,  ReLU
// LAYER 1: in = g_t1,   out = g_t2,  ReLU
// LAYER 2: in = g_t2,   out = d_out, + residual(feats)
// ---------------------------------------------------------------------------
template <int LAYER>
__global__ void __launch_bounds__(256)
sconv_kernel(const float* __restrict__ feats0, const float* __restrict__ feats1,
             const float* __restrict__ W0, const float* __restrict__ W1,
             float* __restrict__ out)
{
    __shared__ float sw[2][KK * CC * CC];
    {
        const float* w0 = W0 + LAYER * KK * CC * CC;
        const float* w1 = W1 + LAYER * KK * CC * CC;
        for (int t = threadIdx.x; t < KK * CC * CC; t += blockDim.x) {
            sw[0][t] = w0[t];
            sw[1][t] = w1[t];
        }
    }
    __syncthreads();

    long long row = (long long)blockIdx.x * blockDim.x + threadIdx.x;
    if (row >= 2LL * NV) return;

    const int g = (row >= NV) ? 1 : 0;
    const int i = (int)(row - (g ? NV : 0));

    const float* xin;
    if (LAYER == 0)      xin = g ? feats1 : feats0;
    else if (LAYER == 1) xin = g_t1 + (size_t)g * NV * CC;
    else                 xin = g_t2 + (size_t)g * NV * CC;

    // Preload all 27 tap indices: coalesced (tap-major layout), fully
    // independent -> one burst of 27 LDG.32 in flight.
    const int* __restrict__ nb = g_nbrt[g];
    int idx[KK];
#pragma unroll
    for (int k = 0; k < KK; k++)
        idx[k] = nb[(size_t)k * NV + i];

    const float* w = sw[g];

    float acc[CC];
#pragma unroll
    for (int d = 0; d < CC; d++) acc[d] = 0.0f;

#pragma unroll
    for (int k = 0; k < KK; k++) {
        if (idx[k] >= 0) {
            const float4* gp = (const float4*)(xin + (size_t)idx[k] * CC);
            float4 a = gp[0];
            float4 b = gp[1];
            float gv[CC] = {a.x, a.y, a.z, a.w, b.x, b.y, b.z, b.w};
            const float* wk = w + k * CC * CC;
#pragma unroll
            for (int c = 0; c < CC; c++) {
#pragma unroll
                for (int d = 0; d < CC; d++) {
                    acc[d] = fmaf(gv[c], wk[c * CC + d], acc[d]);
                }
            }
        }
    }

    if (LAYER < 2) {
#pragma unroll
        for (int d = 0; d < CC; d++) acc[d] = fmaxf(acc[d], 0.0f);
    } else {
        const float* r = (g ? feats1 : feats0) + (size_t)i * CC;
#pragma unroll
        for (int d = 0; d < CC; d++) acc[d] += r[d];
    }

    float* op = (LAYER == 0) ? g_t1 : (LAYER == 1) ? g_t2 : out;
    float4* o4 = (float4*)(op + (size_t)row * CC);
    o4[0] = make_float4(acc[0], acc[1], acc[2], acc[3]);
    o4[1] = make_float4(acc[4], acc[5], acc[6], acc[7]);
}

extern "C" void kernel_launch(void* const* d_in, const int* in_sizes, int n_in,
                              void* d_out, int out_size)
{
    const float* feats0 = (const float*)d_in[0];
    const float* feats1 = (const float*)d_in[1];
    const float* W0     = (const float*)d_in[2];
    const float* W1     = (const float*)d_in[3];
    const int*   nbr0   = (const int*)d_in[4];
    const int*   nbr1   = (const int*)d_in[5];
    float*       out    = (float*)d_out;

    {
        dim3 grid(NV / 32, 2);
        nbr_transpose_kernel<<<grid, 256>>>(nbr0, nbr1);
    }

    const int threads = 256;
    const int blocks  = (2 * NV + threads - 1) / threads;

    sconv_kernel<0><<<blocks, threads>>>(feats0, feats1, W0, W1, out);
    sconv_kernel<1><<<blocks, threads>>>(feats0, feats1, W0, W1, out);
    sconv_kernel<2><<<blocks, threads>>>(feats0, feats1, W0, W1, out);
}